// round 6
// baseline (speedup 1.0000x reference)
#include <cuda_runtime.h>
#include <math.h>
#include <stdint.h>

#define N_PTS 8192
#define D_DIM 256
#define NUM_CLS 64
#define EPSF  1e-10f

#define BT 128                    // CTA tile M = N
#define BK 32                     // K chunk (floats) = 128 B per row
#define NCHUNK (D_DIM / BK)       // 8
#define NSTAGE 3
#define ROWB 144                  // padded row stride in bytes (36 floats)
#define OP_BYTES (BT * ROWB)      // 18432 per operand per stage
#define STAGE_BYTES (2 * OP_BYTES)
#define STAGE_TX (2 * BT * (BK * 4))   // 32768 real bytes per stage
#define MBAR_OFF (NSTAGE * STAGE_BYTES)
#define AUX_OFF (MBAR_OFF + 64)
#define SMEM_TOTAL (AUX_OFF + 4 * BT * 4)
#define N_TILES (N_PTS / BT)      // 64
#define N_CTAS (N_TILES * (N_TILES + 1) / 2)  // 2080

__device__ float g_sq[N_PTS];
__device__ float g_pos[N_PTS];
__device__ float g_neg[N_PTS];
__device__ int   g_cls[N_PTS];
__device__ int   g_done = 0;

static __device__ __forceinline__ uint32_t smem_u32(const void* p) {
    uint32_t a;
    asm("{ .reg .u64 t; cvta.to.shared.u64 t, %1; cvt.u32.u64 %0, t; }"
        : "=r"(a) : "l"(p));
    return a;
}
static __device__ __forceinline__ void bulk_cp(uint32_t dst, const void* src,
                                               uint32_t bytes, uint32_t mbar) {
    asm volatile(
        "cp.async.bulk.shared::cta.global.mbarrier::complete_tx::bytes "
        "[%0], [%1], %2, [%3];"
        :: "r"(dst), "l"(src), "r"(bytes), "r"(mbar) : "memory");
}
static __device__ __forceinline__ void mbar_init(uint32_t addr, uint32_t cnt) {
    asm volatile("mbarrier.init.shared.b64 [%0], %1;" :: "r"(addr), "r"(cnt) : "memory");
}
static __device__ __forceinline__ void mbar_expect_tx(uint32_t addr, uint32_t bytes) {
    asm volatile("mbarrier.arrive.expect_tx.shared.b64 _, [%0], %1;"
                 :: "r"(addr), "r"(bytes) : "memory");
}
static __device__ __forceinline__ void mbar_wait(uint32_t addr, uint32_t parity) {
    asm volatile(
        "{\n\t.reg .pred P;\n"
        "WL_%=:\n\t"
        "mbarrier.try_wait.parity.acquire.cta.shared::cta.b64 P, [%0], %1, 0x989680;\n\t"
        "@P bra WD_%=;\n\t"
        "bra WL_%=;\n"
        "WD_%=:\n\t}"
        :: "r"(addr), "r"(parity) : "memory");
}
#define FENCE_ASYNC_SHARED() asm volatile("fence.proxy.async.shared::cta;" ::: "memory")

static __device__ __forceinline__ void ldsm4(uint32_t* r, uint32_t addr) {
    asm volatile("ldmatrix.sync.aligned.m8n8.x4.shared.b16 {%0,%1,%2,%3}, [%4];"
                 : "=r"(r[0]), "=r"(r[1]), "=r"(r[2]), "=r"(r[3]) : "r"(addr));
}
static __device__ __forceinline__ void mma_tf32(float* c, const uint32_t* a,
                                                const uint32_t* b) {
    asm volatile(
        "mma.sync.aligned.m16n8k8.row.col.f32.tf32.tf32.f32 "
        "{%0,%1,%2,%3}, {%4,%5,%6,%7}, {%8,%9}, {%0,%1,%2,%3};"
        : "+f"(c[0]), "+f"(c[1]), "+f"(c[2]), "+f"(c[3])
        : "r"(a[0]), "r"(a[1]), "r"(a[2]), "r"(a[3]), "r"(b[0]), "r"(b[1]));
}

// ---------------------------------------------------------------------------
// Kernel 1: squared norms + inline dtype detect + class load + accum zero.
// Dtype scan: each warp reads the first 128 int64 words (1KB, L2-resident).
// If target were int32, some odd-position class (high word) is nonzero.
// ---------------------------------------------------------------------------
__global__ void prep_kernel(const float* __restrict__ pred,
                            const void* __restrict__ tgt) {
    int warp = (blockIdx.x * blockDim.x + threadIdx.x) >> 5;
    int lane = threadIdx.x & 31;
    if (warp >= N_PTS) return;

    const long long* t64 = (const long long*)tgt;
    int bad = 0;
#pragma unroll
    for (int q = 0; q < 4; ++q) {
        long long v = t64[lane + 32 * q];
        bad |= (v < 0 || v >= (long long)NUM_CLS);
    }
    bool is64 = (__ballot_sync(0xffffffffu, bad) == 0u);

    const float4* row = (const float4*)(pred + (size_t)warp * D_DIM);
    float s = 0.f;
#pragma unroll
    for (int q = 0; q < 2; ++q) {
        float4 v = row[lane + 32 * q];
        s += v.x * v.x + v.y * v.y + v.z * v.z + v.w * v.w;
    }
#pragma unroll
    for (int o = 16; o; o >>= 1) s += __shfl_xor_sync(0xffffffffu, s, o);
    if (lane == 0) {
        g_sq[warp]  = s;
        g_pos[warp] = 0.f;
        g_neg[warp] = 0.f;
        g_cls[warp] = is64 ? (int)t64[warp] : ((const int*)tgt)[warp];
    }
}

// ---------------------------------------------------------------------------
// Kernel 2: tf32 mma.sync Gram tile, cp.async.bulk staging, fused epilogue,
// folded finalize. Triangular 1D grid, 3-stage mbarrier pipeline.
// ---------------------------------------------------------------------------
__global__ __launch_bounds__(256, 2)
void tile_kernel(const float* __restrict__ pred,
                 const float* __restrict__ tempPtr,
                 float* __restrict__ out) {
    // decode triangular index t -> (bi, bj), bi <= bj
    int t = blockIdx.x;
    int bi = (int)((129.0f - sqrtf(16641.0f - 8.0f * (float)t)) * 0.5f);
    while ((bi + 1) * (129 - (bi + 1)) / 2 <= t) ++bi;
    while (bi * (129 - bi) / 2 > t) --bi;
    int bj = bi + (t - bi * (129 - bi) / 2);

    extern __shared__ char smc[];
    uint32_t sbase = smem_u32(smc);
    uint32_t mbarB = sbase + MBAR_OFF;
    float* sqR = (float*)(smc + AUX_OFF);
    float* sqC = sqR + BT;
    int*   clR = (int*)(sqC + BT);
    int*   clC = clR + BT;

    int tid  = threadIdx.x;
    int lane = tid & 31, wid = tid >> 5;
    int wm = wid & 1, wn = wid >> 1;              // 2 x 4 warp grid
    int R0 = wm * 64, C0 = wn * 32;
    int gq = lane >> 2, tq = lane & 3;
    int i0 = bi * BT, j0 = bj * BT;

    if (tid == 0) {
#pragma unroll
        for (int s = 0; s < NSTAGE; ++s) mbar_init(mbarB + s * 8, 1);
    }
    if (tid < BT) {
        sqR[tid] = g_sq[i0 + tid];
        sqC[tid] = g_sq[j0 + tid];
        clR[tid] = g_cls[i0 + tid];
        clC[tid] = g_cls[j0 + tid];
    }
    __syncthreads();
    FENCE_ASYNC_SHARED();

    // per-thread bulk-copy role: one 128B row-chunk per chunk issue
    int cp_op  = tid >> 7;                        // 0 = A, 1 = B
    int cp_row = tid & 127;
    const float* cp_src = pred + (size_t)((cp_op ? j0 : i0) + cp_row) * D_DIM;
    uint32_t cp_dst = cp_op * OP_BYTES + (uint32_t)cp_row * ROWB;

    auto issue = [&](int stage, int k0) {
        if (tid == 0) mbar_expect_tx(mbarB + stage * 8, STAGE_TX);
        bulk_cp(sbase + stage * STAGE_BYTES + cp_dst, cp_src + k0,
                BK * 4, mbarB + stage * 8);
    };

    // ldmatrix byte offsets within a stage
    uint32_t offA = (uint32_t)((R0 + (lane & 15)) * ROWB + (lane >> 4) * 16);
    uint32_t offB = OP_BYTES +
        (uint32_t)((C0 + (lane >> 4) * 8 + (lane & 7)) * ROWB + ((lane >> 3) & 1) * 16);

    float acc[4][4][4];
#pragma unroll
    for (int mi = 0; mi < 4; mi++)
#pragma unroll
        for (int ni = 0; ni < 4; ni++)
#pragma unroll
            for (int v = 0; v < 4; v++) acc[mi][ni][v] = 0.f;

    issue(0, 0);
    issue(1, BK);
#pragma unroll 1
    for (int c = 0; c < NCHUNK; ++c) {
        mbar_wait(mbarB + (c % NSTAGE) * 8, (c / NSTAGE) & 1);
        __syncthreads();                          // all warps done with stage c-1
        if (c + 2 < NCHUNK) issue((c + 2) % NSTAGE, (c + 2) * BK);

        uint32_t sA = sbase + (uint32_t)((c % NSTAGE) * STAGE_BYTES);
#pragma unroll
        for (int ks = 0; ks < 4; ++ks) {
            uint32_t a[4][4], b[4][2];
#pragma unroll
            for (int mi = 0; mi < 4; mi++)
                ldsm4(a[mi], sA + offA + (uint32_t)(mi * 16 * ROWB + ks * 32));
#pragma unroll
            for (int p = 0; p < 2; p++) {
                uint32_t r[4];
                ldsm4(r, sA + offB + (uint32_t)(p * 16 * ROWB + ks * 32));
                b[2 * p][0] = r[0]; b[2 * p][1] = r[1];
                b[2 * p + 1][0] = r[2]; b[2 * p + 1][1] = r[3];
            }
#pragma unroll
            for (int mi = 0; mi < 4; mi++)
#pragma unroll
                for (int ni = 0; ni < 4; ni++)
                    mma_tf32(acc[mi][ni], a[mi], b[ni]);
        }
    }

    // ---- Epilogue: exp + masked sums on register fragments ----
    float invT = 1.0f / tempPtr[0];
    bool diag  = (bi == bj);

    float rP[8], rN[8], cP[8], cN[8];
#pragma unroll
    for (int q = 0; q < 8; q++) { rP[q] = rN[q] = cP[q] = cN[q] = 0.f; }

#pragma unroll
    for (int mi = 0; mi < 4; mi++)
#pragma unroll
        for (int h = 0; h < 2; h++) {
            int rl = R0 + mi * 16 + gq + h * 8;
            float sqi = sqR[rl];
            int   ci  = clR[rl];
#pragma unroll
            for (int ni = 0; ni < 4; ni++)
#pragma unroll
                for (int w = 0; w < 2; w++) {
                    int cl = C0 + ni * 8 + tq * 2 + w;
                    float dot = acc[mi][ni][h * 2 + w];
                    float pn  = fmaxf(sqi + sqC[cl] - 2.0f * dot, EPSF);
                    float dv  = __expf(-pn * invT);
                    if (diag && rl == cl) dv = 0.f;
                    bool same = (ci == clC[cl]);
                    float p = same ? dv : 0.f;
                    float n = dv - p;
                    rP[mi * 2 + h] += p; rN[mi * 2 + h] += n;
                    cP[ni * 2 + w] += p; cN[ni * 2 + w] += n;
                }
        }

#pragma unroll
    for (int q = 0; q < 8; q++) {
#pragma unroll
        for (int o = 4; o <= 16; o <<= 1) {
            cP[q] += __shfl_xor_sync(0xffffffffu, cP[q], o);
            cN[q] += __shfl_xor_sync(0xffffffffu, cN[q], o);
        }
    }
    if (lane < 4) {
#pragma unroll
        for (int q = 0; q < 8; q++) {
            int cl = C0 + (q >> 1) * 8 + lane * 2 + (q & 1);
            atomicAdd(&g_pos[j0 + cl], cP[q]);
            atomicAdd(&g_neg[j0 + cl], cN[q]);
        }
    }
#pragma unroll
    for (int q = 0; q < 8; q++) {
#pragma unroll
        for (int o = 1; o <= 2; o <<= 1) {
            rP[q] += __shfl_xor_sync(0xffffffffu, rP[q], o);
            rN[q] += __shfl_xor_sync(0xffffffffu, rN[q], o);
        }
    }
    if (!diag && tq == 0) {
#pragma unroll
        for (int q = 0; q < 8; q++) {
            int rl = R0 + (q >> 1) * 16 + gq + (q & 1) * 8;
            atomicAdd(&g_pos[i0 + rl], rP[q]);
            atomicAdd(&g_neg[i0 + rl], rN[q]);
        }
    }

    // ---- Folded finalize: last CTA to finish reduces the loss ----
    __shared__ int s_last;
    __syncthreads();
    if (tid == 0) {
        __threadfence();
        s_last = (atomicAdd(&g_done, 1) == N_CTAS - 1);
    }
    __syncthreads();
    if (s_last) {
        __threadfence();
        __shared__ float red[8];
        float s = 0.f;
        for (int j = tid; j < N_PTS; j += 256) {
            float num = g_pos[j];
            float den = fmaxf(g_neg[j], EPSF);
            float frac = num / (num + den);
            if (frac >= EPSF) s += logf(frac);
        }
#pragma unroll
        for (int o = 16; o; o >>= 1) s += __shfl_xor_sync(0xffffffffu, s, o);
        if (lane == 0) red[wid] = s;
        __syncthreads();
        if (tid < 8) {
            float v = red[tid];
#pragma unroll
            for (int o = 4; o; o >>= 1) v += __shfl_xor_sync(0xffu, v, o);
            if (tid == 0) {
                out[0] = -v / (float)N_PTS;
                g_done = 0;   // reset for deterministic graph replay
            }
        }
    }
}

// ---------------------------------------------------------------------------
extern "C" void kernel_launch(void* const* d_in, const int* in_sizes, int n_in,
                              void* d_out, int out_size) {
    const float* pred = (const float*)d_in[0];
    const void*  tgt  = d_in[1];
    const float* temp = (const float*)d_in[2];

    cudaFuncSetAttribute(tile_kernel,
                         cudaFuncAttributeMaxDynamicSharedMemorySize, SMEM_TOTAL);

    prep_kernel<<<(N_PTS * 32 + 255) / 256, 256>>>(pred, tgt);
    tile_kernel<<<N_CTAS, 256, SMEM_TOTAL>>>(pred, temp, (float*)d_out);
}

// round 7
// speedup vs baseline: 1.8195x; 1.8195x over previous
#include <cuda_runtime.h>
#include <cuda_bf16.h>
#include <math.h>
#include <stdint.h>

#define N_PTS 8192
#define D_DIM 256
#define NUM_CLS 64
#define EPSF  1e-10f

#define BT 128                    // CTA tile M = N
#define BKE 64                    // K chunk in bf16 elems = 128 B per row
#define NCHUNK (D_DIM / BKE)      // 4
#define NSTAGE 3
#define ROWB 144                  // padded row stride in bytes (72 bf16)
#define STAGE_BYTES (256 * ROWB)  // A rows 0-127, B rows 128-255
#define AUX_OFF (NSTAGE * STAGE_BYTES)
#define SMEM_TOTAL (AUX_OFF + 4 * BT * 4)
#define N_TILES (N_PTS / BT)      // 64
#define N_CTAS (N_TILES * (N_TILES + 1) / 2)  // 2080

__device__ float g_sq[N_PTS];
__device__ float g_pos[N_PTS];
__device__ float g_neg[N_PTS];
__device__ int   g_cls[N_PTS];
__device__ int   g_done = 0;
__device__ __nv_bfloat16 g_bf[N_PTS * D_DIM];   // bf16 copy of pred

static __device__ __forceinline__ uint32_t smem_u32(const void* p) {
    uint32_t a;
    asm("{ .reg .u64 t; cvta.to.shared.u64 t, %1; cvt.u32.u64 %0, t; }"
        : "=r"(a) : "l"(p));
    return a;
}
static __device__ __forceinline__ void cp16(uint32_t dst, const void* src) {
    asm volatile("cp.async.cg.shared.global [%0], [%1], 16;"
                 :: "r"(dst), "l"(src) : "memory");
}
#define CP_COMMIT() asm volatile("cp.async.commit_group;" ::: "memory")
#define CP_WAIT(n)  asm volatile("cp.async.wait_group %0;" :: "n"(n) : "memory")

static __device__ __forceinline__ void ldsm4(uint32_t* r, uint32_t addr) {
    asm volatile("ldmatrix.sync.aligned.m8n8.x4.shared.b16 {%0,%1,%2,%3}, [%4];"
                 : "=r"(r[0]), "=r"(r[1]), "=r"(r[2]), "=r"(r[3]) : "r"(addr));
}
static __device__ __forceinline__ void mma_bf16(float* c, const uint32_t* a,
                                                const uint32_t* b) {
    asm volatile(
        "mma.sync.aligned.m16n8k16.row.col.f32.bf16.bf16.f32 "
        "{%0,%1,%2,%3}, {%4,%5,%6,%7}, {%8,%9}, {%0,%1,%2,%3};"
        : "+f"(c[0]), "+f"(c[1]), "+f"(c[2]), "+f"(c[3])
        : "r"(a[0]), "r"(a[1]), "r"(a[2]), "r"(a[3]), "r"(b[0]), "r"(b[1]));
}

// ---------------------------------------------------------------------------
// Kernel 1: squared norms (exact fp32) + bf16 conversion + dtype detect +
// class load + accumulator zero. One warp per row.
// ---------------------------------------------------------------------------
__global__ void prep_kernel(const float* __restrict__ pred,
                            const void* __restrict__ tgt) {
    int warp = (blockIdx.x * blockDim.x + threadIdx.x) >> 5;
    int lane = threadIdx.x & 31;
    if (warp >= N_PTS) return;

    // dtype scan on first 1KB (L2-resident): int32 data shows values >= 64
    const long long* t64 = (const long long*)tgt;
    int bad = 0;
#pragma unroll
    for (int q = 0; q < 4; ++q) {
        long long v = t64[lane + 32 * q];
        bad |= (v < 0 || v >= (long long)NUM_CLS);
    }
    bool is64 = (__ballot_sync(0xffffffffu, bad) == 0u);

    const float4* row = (const float4*)(pred + (size_t)warp * D_DIM);
    float s = 0.f;
#pragma unroll
    for (int q = 0; q < 2; ++q) {
        float4 v = row[lane + 32 * q];
        s += v.x * v.x + v.y * v.y + v.z * v.z + v.w * v.w;
        __nv_bfloat162 p0 = __float22bfloat162_rn(make_float2(v.x, v.y));
        __nv_bfloat162 p1 = __float22bfloat162_rn(make_float2(v.z, v.w));
        uint2 u;
        u.x = *(uint32_t*)&p0; u.y = *(uint32_t*)&p1;
        *(uint2*)(g_bf + (size_t)warp * D_DIM + 4 * (lane + 32 * q)) = u;
    }
#pragma unroll
    for (int o = 16; o; o >>= 1) s += __shfl_xor_sync(0xffffffffu, s, o);
    if (lane == 0) {
        g_sq[warp]  = s;
        g_pos[warp] = 0.f;
        g_neg[warp] = 0.f;
        g_cls[warp] = is64 ? (int)t64[warp] : ((const int*)tgt)[warp];
    }
}

// ---------------------------------------------------------------------------
// Kernel 2: bf16 m16n8k16 Gram tile + fused epilogue + folded finalize.
// Triangular 1D grid; cp.async 3-stage pipeline; ldmatrix fragments.
// ---------------------------------------------------------------------------
__global__ __launch_bounds__(256, 2)
void tile_kernel(const float* __restrict__ tempPtr,
                 float* __restrict__ out) {
    // decode triangular index t -> (bi, bj), bi <= bj
    int t = blockIdx.x;
    int bi = (int)((129.0f - sqrtf(16641.0f - 8.0f * (float)t)) * 0.5f);
    while ((bi + 1) * (129 - (bi + 1)) / 2 <= t) ++bi;
    while (bi * (129 - bi) / 2 > t) --bi;
    int bj = bi + (t - bi * (129 - bi) / 2);

    extern __shared__ char smc[];
    uint32_t sbase = smem_u32(smc);
    float* sqR = (float*)(smc + AUX_OFF);
    float* sqC = sqR + BT;
    int*   clR = (int*)(sqC + BT);
    int*   clC = clR + BT;

    int tid  = threadIdx.x;
    int lane = tid & 31, wid = tid >> 5;
    int wm = wid & 1, wn = wid >> 1;              // 2 x 4 warp grid
    int R0 = wm * 64, C0 = wn * 32;
    int gq = lane >> 2, tq = lane & 3;
    int i0 = bi * BT, j0 = bj * BT;

    if (tid < BT) {
        sqR[tid] = g_sq[i0 + tid];
        sqC[tid] = g_sq[j0 + tid];
        clR[tid] = g_cls[i0 + tid];
        clC[tid] = g_cls[j0 + tid];
    }

    // per-thread cp.async role: 8 x 16B per chunk; row = tid>>3 + 32i
    int seg = tid & 7;                            // 16B segment within 128B
    int rbase = tid >> 3;                         // 0..31
    const __nv_bfloat16* srcA = g_bf + (size_t)i0 * D_DIM;
    const __nv_bfloat16* srcB = g_bf + (size_t)j0 * D_DIM;

    auto issue = [&](int stage, int k0) {
        uint32_t sdst = sbase + (uint32_t)(stage * STAGE_BYTES) + seg * 16u;
#pragma unroll
        for (int i = 0; i < 8; ++i) {
            int row = rbase + 32 * i;             // 0..255
            const __nv_bfloat16* src = (row < 128)
                ? srcA + (size_t)row * D_DIM
                : srcB + (size_t)(row - 128) * D_DIM;
            cp16(sdst + (uint32_t)row * ROWB, src + k0 + seg * 8);
        }
        CP_COMMIT();
    };

    // ldmatrix byte offsets within a stage (same lane formulas as tf32 ver.)
    uint32_t offA = (uint32_t)((R0 + (lane & 15)) * ROWB + (lane >> 4) * 16);
    uint32_t offB = (uint32_t)((128 + C0 + (lane >> 4) * 8 + (lane & 7)) * ROWB
                               + ((lane >> 3) & 1) * 16);

    float acc[4][4][4];
#pragma unroll
    for (int mi = 0; mi < 4; mi++)
#pragma unroll
        for (int ni = 0; ni < 4; ni++)
#pragma unroll
            for (int v = 0; v < 4; v++) acc[mi][ni][v] = 0.f;

    issue(0, 0);
    issue(1, BKE);
#pragma unroll 1
    for (int c = 0; c < NCHUNK; ++c) {
        if (c < NCHUNK - 1) CP_WAIT(1); else CP_WAIT(0);
        __syncthreads();
        if (c + 2 < NCHUNK) issue((c + 2) % NSTAGE, (c + 2) * BKE);

        uint32_t sA = sbase + (uint32_t)((c % NSTAGE) * STAGE_BYTES);
#pragma unroll
        for (int ks = 0; ks < 4; ++ks) {          // k16 steps within 64-chunk
            uint32_t a[4][4], b[4][2];
#pragma unroll
            for (int mi = 0; mi < 4; mi++)
                ldsm4(a[mi], sA + offA + (uint32_t)(mi * 16 * ROWB + ks * 32));
#pragma unroll
            for (int p = 0; p < 2; p++) {
                uint32_t r[4];
                ldsm4(r, sA + offB + (uint32_t)(p * 16 * ROWB + ks * 32));
                b[2 * p][0] = r[0]; b[2 * p][1] = r[1];
                b[2 * p + 1][0] = r[2]; b[2 * p + 1][1] = r[3];
            }
#pragma unroll
            for (int mi = 0; mi < 4; mi++)
#pragma unroll
                for (int ni = 0; ni < 4; ni++)
                    mma_bf16(acc[mi][ni], a[mi], b[ni]);
        }
    }

    // ---- Epilogue: exp + masked sums on register fragments ----
    float invT = 1.0f / tempPtr[0];
    bool diag  = (bi == bj);

    float rP[8], rN[8], cP[8], cN[8];
#pragma unroll
    for (int q = 0; q < 8; q++) { rP[q] = rN[q] = cP[q] = cN[q] = 0.f; }

#pragma unroll
    for (int mi = 0; mi < 4; mi++)
#pragma unroll
        for (int h = 0; h < 2; h++) {
            int rl = R0 + mi * 16 + gq + h * 8;
            float sqi = sqR[rl];
            int   ci  = clR[rl];
#pragma unroll
            for (int ni = 0; ni < 4; ni++)
#pragma unroll
                for (int w = 0; w < 2; w++) {
                    int cl = C0 + ni * 8 + tq * 2 + w;
                    float dot = acc[mi][ni][h * 2 + w];
                    float pn  = fmaxf(sqi + sqC[cl] - 2.0f * dot, EPSF);
                    float dv  = __expf(-pn * invT);
                    if (diag && rl == cl) dv = 0.f;
                    bool same = (ci == clC[cl]);
                    float p = same ? dv : 0.f;
                    float n = dv - p;
                    rP[mi * 2 + h] += p; rN[mi * 2 + h] += n;
                    cP[ni * 2 + w] += p; cN[ni * 2 + w] += n;
                }
        }

#pragma unroll
    for (int q = 0; q < 8; q++) {
#pragma unroll
        for (int o = 4; o <= 16; o <<= 1) {
            cP[q] += __shfl_xor_sync(0xffffffffu, cP[q], o);
            cN[q] += __shfl_xor_sync(0xffffffffu, cN[q], o);
        }
    }
    if (lane < 4) {
#pragma unroll
        for (int q = 0; q < 8; q++) {
            int cl = C0 + (q >> 1) * 8 + lane * 2 + (q & 1);
            atomicAdd(&g_pos[j0 + cl], cP[q]);
            atomicAdd(&g_neg[j0 + cl], cN[q]);
        }
    }
#pragma unroll
    for (int q = 0; q < 8; q++) {
#pragma unroll
        for (int o = 1; o <= 2; o <<= 1) {
            rP[q] += __shfl_xor_sync(0xffffffffu, rP[q], o);
            rN[q] += __shfl_xor_sync(0xffffffffu, rN[q], o);
        }
    }
    if (!diag && tq == 0) {
#pragma unroll
        for (int q = 0; q < 8; q++) {
            int rl = R0 + (q >> 1) * 16 + gq + (q & 1) * 8;
            atomicAdd(&g_pos[i0 + rl], rP[q]);
            atomicAdd(&g_neg[i0 + rl], rN[q]);
        }
    }

    // ---- Folded finalize: last CTA to finish reduces the loss ----
    __shared__ int s_last;
    __syncthreads();
    if (tid == 0) {
        __threadfence();
        s_last = (atomicAdd(&g_done, 1) == N_CTAS - 1);
    }
    __syncthreads();
    if (s_last) {
        __threadfence();
        __shared__ float red[8];
        float s = 0.f;
        for (int j = tid; j < N_PTS; j += 256) {
            float num = g_pos[j];
            float den = fmaxf(g_neg[j], EPSF);
            float frac = num / (num + den);
            if (frac >= EPSF) s += logf(frac);
        }
#pragma unroll
        for (int o = 16; o; o >>= 1) s += __shfl_xor_sync(0xffffffffu, s, o);
        if (lane == 0) red[wid] = s;
        __syncthreads();
        if (tid < 8) {
            float v = red[tid];
#pragma unroll
            for (int o = 4; o; o >>= 1) v += __shfl_xor_sync(0xffu, v, o);
            if (tid == 0) {
                out[0] = -v / (float)N_PTS;
                g_done = 0;   // reset for deterministic graph replay
            }
        }
    }
}

// ---------------------------------------------------------------------------
extern "C" void kernel_launch(void* const* d_in, const int* in_sizes, int n_in,
                              void* d_out, int out_size) {
    const float* pred = (const float*)d_in[0];
    const void*  tgt  = d_in[1];
    const float* temp = (const float*)d_in[2];

    cudaFuncSetAttribute(tile_kernel,
                         cudaFuncAttributeMaxDynamicSharedMemorySize, SMEM_TOTAL);

    prep_kernel<<<(N_PTS * 32 + 255) / 256, 256>>>(pred, tgt);
    tile_kernel<<<N_CTAS, 256, SMEM_TOTAL>>>(temp, (float*)d_out);
}